// round 13
// baseline (speedup 1.0000x reference)
#include <cuda_runtime.h>
#include <cmath>
#include <cstdint>

#define BB 4
#define NN 4096
#define CC 256
#define KK 512
#define KNNK 32

// ---------------- scratch (no allocations allowed) ----------------
__device__ float    g_dist[(size_t)BB * NN * NN];   // 268 MB pairwise distances
__device__ float    g_x2[BB * NN];
__device__ float    g_density[BB * NN];
__device__ float    g_score[BB * NN];
__device__ unsigned g_maxbits[BB];
__device__ int      g_index_down[BB * KK];

// ---------------- threefry2x32 (bit-exact JAX PRNG, key = (0,1)) ----------------
__device__ __forceinline__ unsigned rotl32(unsigned x, int r) {
    return (x << r) | (x >> (32 - r));
}

__device__ void threefry2x32(unsigned k1, unsigned k2, unsigned x0, unsigned x1,
                             unsigned& o0, unsigned& o1) {
    unsigned ks0 = k1, ks1 = k2, ks2 = k1 ^ k2 ^ 0x1BD11BDAu;
    const int ra[4] = {13, 15, 26, 6};
    const int rb[4] = {17, 29, 16, 24};
    x0 += ks0; x1 += ks1;
#pragma unroll
    for (int i = 0; i < 4; i++) { x0 += x1; x1 = rotl32(x1, ra[i]); x1 ^= x0; }
    x0 += ks1; x1 += ks2 + 1u;
#pragma unroll
    for (int i = 0; i < 4; i++) { x0 += x1; x1 = rotl32(x1, rb[i]); x1 ^= x0; }
    x0 += ks2; x1 += ks0 + 2u;
#pragma unroll
    for (int i = 0; i < 4; i++) { x0 += x1; x1 = rotl32(x1, ra[i]); x1 ^= x0; }
    x0 += ks0; x1 += ks1 + 3u;
#pragma unroll
    for (int i = 0; i < 4; i++) { x0 += x1; x1 = rotl32(x1, rb[i]); x1 ^= x0; }
    x0 += ks1; x1 += ks2 + 4u;
#pragma unroll
    for (int i = 0; i < 4; i++) { x0 += x1; x1 = rotl32(x1, ra[i]); x1 ^= x0; }
    x0 += ks2; x1 += ks0 + 5u;
    o0 = x0; o1 = x1;
}

// JAX threefry_partitionable random_bits (32-bit): counter = uint64 iota ->
// threefry2x32(key, 0, i), bits = o0 ^ o1. uniform = bitcast((bits>>9)|1.0f)-1.
__device__ float jax_uniform_noise(unsigned gid) {
    unsigned o0, o1;
    threefry2x32(0u, 1u, 0u, gid, o0, o1);
    unsigned bits = o0 ^ o1;
    unsigned fb = (bits >> 9) | 0x3f800000u;
    return __uint_as_float(fb) - 1.0f;
}

// ---------------- glibc expf (bit-exact port of sysdeps/ieee754/flt-32/e_expf.c) ----
__device__ __constant__ unsigned long long c_exp_tab[32] = {
    0x3ff0000000000000ULL, 0x3fefd9b0d3158574ULL, 0x3fefb5586cf9890fULL, 0x3fef9301d0125b51ULL,
    0x3fef72b83c7d517bULL, 0x3fef54873168b9aaULL, 0x3fef387a6e756238ULL, 0x3fef1e9df51fdee1ULL,
    0x3fef06fe0a31b715ULL, 0x3feef1a7373aa9cbULL, 0x3feedea64c123422ULL, 0x3feece086061892dULL,
    0x3feebfdad5362a27ULL, 0x3feeb42b569d4f82ULL, 0x3feeab07dd485429ULL, 0x3feea47eb03a5585ULL,
    0x3feea09e667f3bcdULL, 0x3fee9f75e8ec5f74ULL, 0x3feea11473eb0187ULL, 0x3feea589994cce13ULL,
    0x3feeace5422aa0dbULL, 0x3feeb737b0cdc5e5ULL, 0x3feec49182a3f090ULL, 0x3feed503b23e255dULL,
    0x3feee89f995ad3adULL, 0x3feeff76f2fb5e47ULL, 0x3fef199bdd85529cULL, 0x3fef3720dcef9069ULL,
    0x3fef5818dcfba487ULL, 0x3fef7c97337b9b5fULL, 0x3fefa4afa2a490daULL, 0x3fefd0765b6e4540ULL
};

__device__ float glibc_expf(float x) {
    const double InvLn2N = 0x1.71547652b82fep+5;          // N/ln2, N=32
    const double C0 = 0x1.c6af84b912394p-5 / (32.0 * 32.0 * 32.0);
    const double C1 = 0x1.ebfce50fac4f3p-3 / (32.0 * 32.0);
    const double C2 = 0x1.62e42ff0c52d6p-1 / 32.0;
    double xd = (double)x;
    double z  = InvLn2N * xd;
    double kd = rint(z);
    long long kis = __double2ll_rn(z);
    unsigned long long ki = (unsigned long long)kis;
    double r = z - kd;
    unsigned long long t = c_exp_tab[ki & 31] + (ki << 47);
    double s = __longlong_as_double((long long)t);
    double zz = fma(C0, r, C1);
    double r2 = r * r;
    double y  = fma(C2, r, 1.0);
    y = fma(zz, r2, y);
    return (float)(y * s);
}

// ---------------- f32x2 packed helpers ----------------
__device__ __forceinline__ unsigned long long pack_dup_f32(float a) {
    unsigned long long r;
    unsigned ai = __float_as_uint(a);
    asm("mov.b64 %0, {%1, %1};" : "=l"(r) : "r"(ai));
    return r;
}
__device__ __forceinline__ void fma2(unsigned long long& acc, unsigned long long a,
                                     unsigned long long b) {
    asm("fma.rn.f32x2 %0, %1, %2, %0;" : "+l"(acc) : "l"(a), "l"(b));
}
__device__ __forceinline__ void unpack2(unsigned long long v, float& lo, float& hi) {
    unsigned l, h;
    asm("mov.b64 {%0, %1}, %2;" : "=r"(l), "=r"(h) : "l"(v));
    lo = __uint_as_float(l); hi = __uint_as_float(h);
}

// ---------------- kernels ----------------

// no-op: shifts the ncu capture ordinal so knn_density_kernel gets profiled
__global__ void nop_kernel() {}

// x2 = sum(x*x, -1): 4 lane accumulators over k mod 4, unfused mul+add,
// horizontal combine (a0+a2)+(a1+a3). Also resets g_maxbits.
__global__ void x2_kernel(const float* __restrict__ x) {
    int row = blockIdx.x * blockDim.x + threadIdx.x;
    if (blockIdx.x == 0 && threadIdx.x < BB) g_maxbits[threadIdx.x] = 0u;
    if (row >= BB * NN) return;
    const float4* xp = (const float4*)(x + (size_t)row * CC);
    float a0 = 0.f, a1 = 0.f, a2 = 0.f, a3 = 0.f;
#pragma unroll 8
    for (int kb = 0; kb < CC / 4; kb++) {
        float4 v = xp[kb];
        a0 = __fadd_rn(a0, __fmul_rn(v.x, v.x));
        a1 = __fadd_rn(a1, __fmul_rn(v.y, v.y));
        a2 = __fadd_rn(a2, __fmul_rn(v.z, v.z));
        a3 = __fadd_rn(a3, __fmul_rn(v.w, v.w));
    }
    g_x2[row] = __fadd_rn(__fadd_rn(a0, a2), __fadd_rn(a1, a3));
}

// Triangular distance GEMM, 128x128 block tile, thread tile 8x8, packed
// fma.rn.f32x2, double-buffered smem, XOR-swizzled transpose stores,
// 1 barrier per K-chunk, 2 CTAs/SM. Bit-exact ascending-k chains.
#define NTILE 32            // NN/128
#define NPAIRS 528          // NTILE*(NTILE+1)/2
#define KCH 16
#define NCHUNK (CC / KCH)   // 16
__device__ __forceinline__ int tri_base(int i) { return i * (2 * NTILE + 1 - i) / 2; }

__global__ __launch_bounds__(256, 2) void dist_kernel(const float* __restrict__ x) {
    const int TS = 128;
    int b = blockIdx.z;
    int l = blockIdx.x;
    int ti = (int)((2 * NTILE + 1 - sqrtf((float)((2 * NTILE + 1) * (2 * NTILE + 1) - 8 * l))) * 0.5f);
    if (ti > 0 && tri_base(ti) > l) ti--;
    while (tri_base(ti + 1) <= l) ti++;
    int tj = ti + (l - tri_base(ti));
    int it = ti * TS;
    int jt = tj * TS;
    const float* xb = x + (size_t)b * NN * CC;

    __shared__ __align__(16) float As[2][KCH][TS];   // 16 KB
    __shared__ __align__(16) float Bs[2][KCH][TS];   // 16 KB

    int tid = threadIdx.x;          // 256 threads
    int tx = tid & 15, ty = tid >> 4;

    int rowb  = tid >> 2;           // 0..63
    int kk0   = (tid & 3) * 4;
    int swsto = (tid & 3) << 3;     // store-side swizzle = ((k>>2)&3)<<3
    const float* aptr = &xb[(size_t)(it + rowb) * CC + kk0];
    const float* bptr = &xb[(size_t)(jt + rowb) * CC + kk0];

    unsigned long long acc2[8][4];  // [u][vpair]
#pragma unroll
    for (int u = 0; u < 8; u++)
#pragma unroll
        for (int vp = 0; vp < 4; vp++) acc2[u][vp] = 0ULL;

    float4 pa0, pa1, pb0, pb1;
#define LOAD_CHUNK(k0n)                                 \
    do {                                                \
        pa0 = *(const float4*)(aptr + (k0n));           \
        pa1 = *(const float4*)(aptr + 64 * CC + (k0n)); \
        pb0 = *(const float4*)(bptr + (k0n));           \
        pb1 = *(const float4*)(bptr + 64 * CC + (k0n)); \
    } while (0)

#define STORE_CHUNK(buf)                                          \
    do {                                                          \
        int rc0 = rowb ^ swsto;                                   \
        int rc1 = (rowb + 64) ^ swsto;                            \
        As[buf][kk0 + 0][rc0] = pa0.x; As[buf][kk0 + 1][rc0] = pa0.y; \
        As[buf][kk0 + 2][rc0] = pa0.z; As[buf][kk0 + 3][rc0] = pa0.w; \
        As[buf][kk0 + 0][rc1] = pa1.x; As[buf][kk0 + 1][rc1] = pa1.y; \
        As[buf][kk0 + 2][rc1] = pa1.z; As[buf][kk0 + 3][rc1] = pa1.w; \
        Bs[buf][kk0 + 0][rc0] = pb0.x; Bs[buf][kk0 + 1][rc0] = pb0.y; \
        Bs[buf][kk0 + 2][rc0] = pb0.z; Bs[buf][kk0 + 3][rc0] = pb0.w; \
        Bs[buf][kk0 + 0][rc1] = pb1.x; Bs[buf][kk0 + 1][rc1] = pb1.y; \
        Bs[buf][kk0 + 2][rc1] = pb1.z; Bs[buf][kk0 + 3][rc1] = pb1.w; \
    } while (0)

    LOAD_CHUNK(0);
    STORE_CHUNK(0);
    __syncthreads();

    for (int chunk = 0; chunk < NCHUNK; chunk++) {
        int cur = chunk & 1;
        if (chunk + 1 < NCHUNK) LOAD_CHUNK((chunk + 1) * KCH);
#pragma unroll
        for (int kc = 0; kc < KCH; kc++) {
            const int swz = ((kc >> 2) & 3) << 3;
            float4 a0 = *(const float4*)(&As[cur][kc][(ty * 8) ^ swz]);
            float4 a1 = *(const float4*)(&As[cur][kc][(ty * 8 + 4) ^ swz]);
            double2 bd0 = *(const double2*)(&Bs[cur][kc][(tx * 8) ^ swz]);
            double2 bd1 = *(const double2*)(&Bs[cur][kc][(tx * 8 + 4) ^ swz]);
            unsigned long long b2[4];
            b2[0] = __double_as_longlong(bd0.x);
            b2[1] = __double_as_longlong(bd0.y);
            b2[2] = __double_as_longlong(bd1.x);
            b2[3] = __double_as_longlong(bd1.y);
            float a[8] = {a0.x, a0.y, a0.z, a0.w, a1.x, a1.y, a1.z, a1.w};
#pragma unroll
            for (int u = 0; u < 8; u++) {
                unsigned long long a2 = pack_dup_f32(a[u]);
#pragma unroll
                for (int vp = 0; vp < 4; vp++)
                    fma2(acc2[u][vp], a2, b2[vp]);
            }
        }
        if (chunk + 1 < NCHUNK) {
            STORE_CHUNK(cur ^ 1);
            __syncthreads();
        }
    }

    float acc[8][8];
#pragma unroll
    for (int u = 0; u < 8; u++)
#pragma unroll
        for (int vp = 0; vp < 4; vp++)
            unpack2(acc2[u][vp], acc[u][2 * vp], acc[u][2 * vp + 1]);

    float x2i[8], x2j[8];
#pragma unroll
    for (int u = 0; u < 8; u++) x2i[u] = g_x2[b * NN + it + ty * 8 + u];
#pragma unroll
    for (int v = 0; v < 8; v++) x2j[v] = g_x2[b * NN + jt + tx * 8 + v];
    unsigned mbits = 0u;
#pragma unroll
    for (int u = 0; u < 8; u++) {
#pragma unroll
        for (int v = 0; v < 8; v++) {
            float s  = __fadd_rn(x2i[u], x2j[v]);
            float d2 = __fadd_rn(s, -__fmul_rn(2.0f, acc[u][v]));
            d2 = fmaxf(d2, 0.0f);
            float d = __fmul_rn(__fsqrt_rn(d2), 0.0625f);
            acc[u][v] = d;
            mbits = max(mbits, __float_as_uint(d));
        }
    }
    mbits = __reduce_max_sync(0xffffffffu, mbits);
    if ((tid & 31) == 0) atomicMax(&g_maxbits[b], mbits);

#pragma unroll
    for (int u = 0; u < 8; u++) {
        float* drow = g_dist + ((size_t)b * NN + it + ty * 8 + u) * NN + jt + tx * 8;
        *(float4*)(drow)     = make_float4(acc[u][0], acc[u][1], acc[u][2], acc[u][3]);
        *(float4*)(drow + 4) = make_float4(acc[u][4], acc[u][5], acc[u][6], acc[u][7]);
    }
    if (it != jt) {
#pragma unroll
        for (int v = 0; v < 8; v++) {
            float* drow = g_dist + ((size_t)b * NN + jt + tx * 8 + v) * NN + it + ty * 8;
            *(float4*)(drow)     = make_float4(acc[0][v], acc[1][v], acc[2][v], acc[3][v]);
            *(float4*)(drow + 4) = make_float4(acc[4][v], acc[5][v], acc[6][v], acc[7][v]);
        }
    }
}

// per-row 32 smallest, barrier-free selection:
// phase 1: each warp extracts its own sorted top-32 (redux + ballot, NO block sync)
// phase 2: warp 0 merges the 8x32 candidates in registers; lane 0 accumulates
//          density sum in reference order (ascending, mod-4 lanes, unfused).
__global__ void knn_density_kernel() {
    int row = blockIdx.x;                 // b*NN + i
    const float4* dr4 = (const float4*)(g_dist + (size_t)row * NN);
    int tid  = threadIdx.x;               // 256
    int lane = tid & 31, wid = tid >> 5;
    const unsigned REMOVED = 0xFFFFFFFFu;

    __shared__ unsigned warpsel[8][KNNK];

    unsigned v[16];
#pragma unroll
    for (int i = 0; i < 4; i++) {
        float4 f = dr4[tid + 256 * i];
        v[i * 4 + 0] = __float_as_uint(f.x);
        v[i * 4 + 1] = __float_as_uint(f.y);
        v[i * 4 + 2] = __float_as_uint(f.z);
        v[i * 4 + 3] = __float_as_uint(f.w);
    }
    unsigned tmin = REMOVED;
#pragma unroll
    for (int i = 0; i < 16; i++) tmin = min(tmin, v[i]);

    // phase 1: per-warp top-32 (sync-free)
    for (int it = 0; it < KNNK; it++) {
        unsigned wmin = __reduce_min_sync(0xffffffffu, tmin);
        unsigned ball = __ballot_sync(0xffffffffu, tmin == wmin);
        int owner = __ffs(ball) - 1;
        if (lane == owner) {
            bool removed = false;
            unsigned nm = REMOVED;
#pragma unroll
            for (int i = 0; i < 16; i++) {
                if (!removed && v[i] == wmin) { v[i] = REMOVED; removed = true; }
                nm = min(nm, v[i]);
            }
            tmin = nm;
        }
        if (lane == 0) warpsel[wid][it] = wmin;
    }
    __syncthreads();

    // phase 2: warp 0 merges 256 candidates (8 regs/lane)
    if (wid == 0) {
        unsigned w2[8];
#pragma unroll
        for (int q = 0; q < 8; q++) w2[q] = warpsel[q][lane];
        unsigned tm2 = REMOVED;
#pragma unroll
        for (int q = 0; q < 8; q++) tm2 = min(tm2, w2[q]);

        float a0 = 0.f, a1 = 0.f, a2 = 0.f, a3 = 0.f;
#pragma unroll
        for (int it = 0; it < KNNK; it++) {
            unsigned m = __reduce_min_sync(0xffffffffu, tm2);
            unsigned ball = __ballot_sync(0xffffffffu, tm2 == m);
            int owner = __ffs(ball) - 1;
            if (lane == owner) {
                bool removed = false;
                unsigned nm = REMOVED;
#pragma unroll
                for (int q = 0; q < 8; q++) {
                    if (!removed && w2[q] == m) { w2[q] = REMOVED; removed = true; }
                    nm = min(nm, w2[q]);
                }
                tm2 = nm;
            }
            if (lane == 0) {
                float d = __uint_as_float(m);
                float sq = __fmul_rn(d, d);
                if ((it & 3) == 0) a0 = __fadd_rn(a0, sq);
                else if ((it & 3) == 1) a1 = __fadd_rn(a1, sq);
                else if ((it & 3) == 2) a2 = __fadd_rn(a2, sq);
                else a3 = __fadd_rn(a3, sq);
            }
        }
        if (lane == 0) {
            float sum  = __fadd_rn(__fadd_rn(a0, a2), __fadd_rn(a1, a3));
            float mean = __fmul_rn(sum, 0.03125f);
            float dens = glibc_expf(-mean);
            float noise = jax_uniform_noise((unsigned)row);
            g_density[row] = __fadd_rn(dens, __fmul_rn(noise, 1e-6f));
        }
    }
}

// dist-to-nearest-higher-density (vectorized, order-free min), score = dist*density
__global__ void distmin_kernel() {
    int row = blockIdx.x;
    int b = row >> 12;
    const float4* dr4   = (const float4*)(g_dist + (size_t)row * NN);
    const float4* dens4 = (const float4*)(g_density + b * NN);
    float di   = g_density[row];
    float mv = __uint_as_float(g_maxbits[b]);
    int tid = threadIdx.x;
#pragma unroll
    for (int i = 0; i < 4; i++) {
        float4 d = dr4[tid + 256 * i];
        float4 e = dens4[tid + 256 * i];
        if (e.x > di) mv = fminf(mv, d.x);
        if (e.y > di) mv = fminf(mv, d.y);
        if (e.z > di) mv = fminf(mv, d.z);
        if (e.w > di) mv = fminf(mv, d.w);
    }
    unsigned mb = __reduce_min_sync(0xffffffffu, __float_as_uint(mv));
    __shared__ unsigned sm[8];
    if ((tid & 31) == 0) sm[tid >> 5] = mb;
    __syncthreads();
    if (tid == 0) {
        unsigned mm = sm[0];
#pragma unroll
        for (int w = 1; w < 8; w++) mm = min(mm, sm[w]);
        g_score[row] = __fmul_rn(__uint_as_float(mm), di);
    }
}

// bitonic sort, key = (~score_bits << 32) | idx  -> top-K with lax.top_k ties
__global__ void topk_kernel(float* __restrict__ out_indexdown) {
    __shared__ unsigned long long keys[NN];   // 32 KB
    int b = blockIdx.x;
    int tid = threadIdx.x;                    // 512 threads
    for (int j = tid; j < NN; j += 512) {
        unsigned sb = __float_as_uint(g_score[b * NN + j]);
        keys[j] = ((unsigned long long)(~sb) << 32) | (unsigned)j;
    }
    __syncthreads();
    for (unsigned k = 2; k <= NN; k <<= 1) {
        for (unsigned st = k >> 1; st > 0; st >>= 1) {
            for (unsigned i = tid; i < NN; i += 512) {
                unsigned ixj = i ^ st;
                if (ixj > i) {
                    unsigned long long a = keys[i], c = keys[ixj];
                    bool up = ((i & k) == 0);
                    bool swap = up ? (a > c) : (a < c);
                    if (swap) { keys[i] = c; keys[ixj] = a; }
                }
            }
            __syncthreads();
        }
    }
    int idx = (int)(keys[tid] & 0xFFFFFFFFull);
    g_index_down[b * KK + tid] = idx;
    out_indexdown[b * KK + tid] = (float)idx;
}

// idx_cluster[b,j] = argmin_kk dist[b, center_kk, j]  (first-min, strict <)
__global__ void assign_kernel(float* __restrict__ out_idxcluster) {
    int b = blockIdx.y;
    int j = blockIdx.x * 256 + threadIdx.x;
    __shared__ int cen[KK];
    for (int t = threadIdx.x; t < KK; t += 256) cen[t] = g_index_down[b * KK + t];
    __syncthreads();
    const float* db = g_dist + (size_t)b * NN * NN;
    float best = 3.4e38f; int bi = 0;
    for (int kk = 0; kk < KK; kk++) {
        float v = db[(size_t)cen[kk] * NN + j];
        if (v < best) { best = v; bi = kk; }
    }
    out_idxcluster[b * NN + j] = (float)bi;
}

__global__ void scatter_kernel(float* __restrict__ out_idxcluster) {
    int t = blockIdx.x * 256 + threadIdx.x;
    if (t >= BB * KK) return;
    int b = t >> 9, kk = t & (KK - 1);
    out_idxcluster[b * NN + g_index_down[t]] = (float)kk;
}

__global__ void xdown_kernel(const float* __restrict__ x, float* __restrict__ out_xdown) {
    int t = blockIdx.x * 256 + threadIdx.x;
    if (t >= BB * KK * CC) return;
    int c = t & (CC - 1);
    int rest = t >> 8;
    int kk = rest & (KK - 1);
    int b = rest >> 9;
    out_xdown[t] = x[((size_t)b * NN + g_index_down[b * KK + kk]) * CC + c];
}

// ---------------- launch ----------------
extern "C" void kernel_launch(void* const* d_in, const int* in_sizes, int n_in,
                              void* d_out, int out_size) {
    const float* x = (const float*)d_in[0];
    float* out = (float*)d_out;
    float* out_indexdown  = out;                       // B*K
    float* out_idxcluster = out + BB * KK;             // B*N
    float* out_xdown      = out + BB * KK + BB * NN;   // B*K*C

    x2_kernel<<<(BB * NN + 255) / 256, 256>>>(x);

    dim3 gg(NPAIRS, 1, BB);
    dist_kernel<<<gg, 256>>>(x);

    // shift ncu's fixed 4th-launch capture onto knn_density_kernel
    nop_kernel<<<1, 32>>>();

    knn_density_kernel<<<BB * NN, 256>>>();

    distmin_kernel<<<BB * NN, 256>>>();

    topk_kernel<<<BB, 512>>>(out_indexdown);

    assign_kernel<<<dim3(NN / 256, BB), 256>>>(out_idxcluster);
    scatter_kernel<<<(BB * KK + 255) / 256, 256>>>(out_idxcluster);
    xdown_kernel<<<(BB * KK * CC + 255) / 256, 256>>>(x, out_xdown);
}

// round 14
// speedup vs baseline: 1.6317x; 1.6317x over previous
#include <cuda_runtime.h>
#include <cmath>
#include <cstdint>

#define BB 4
#define NN 4096
#define CC 256
#define KK 512
#define KNNK 32

// ---------------- scratch (no allocations allowed) ----------------
__device__ float    g_dist[(size_t)BB * NN * NN];   // 268 MB pairwise distances
__device__ float    g_x2[BB * NN];
__device__ float    g_density[BB * NN];
__device__ float    g_score[BB * NN];
__device__ unsigned g_maxbits[BB];
__device__ int      g_index_down[BB * KK];

// ---------------- threefry2x32 (bit-exact JAX PRNG, key = (0,1)) ----------------
__device__ __forceinline__ unsigned rotl32(unsigned x, int r) {
    return (x << r) | (x >> (32 - r));
}

__device__ void threefry2x32(unsigned k1, unsigned k2, unsigned x0, unsigned x1,
                             unsigned& o0, unsigned& o1) {
    unsigned ks0 = k1, ks1 = k2, ks2 = k1 ^ k2 ^ 0x1BD11BDAu;
    const int ra[4] = {13, 15, 26, 6};
    const int rb[4] = {17, 29, 16, 24};
    x0 += ks0; x1 += ks1;
#pragma unroll
    for (int i = 0; i < 4; i++) { x0 += x1; x1 = rotl32(x1, ra[i]); x1 ^= x0; }
    x0 += ks1; x1 += ks2 + 1u;
#pragma unroll
    for (int i = 0; i < 4; i++) { x0 += x1; x1 = rotl32(x1, rb[i]); x1 ^= x0; }
    x0 += ks2; x1 += ks0 + 2u;
#pragma unroll
    for (int i = 0; i < 4; i++) { x0 += x1; x1 = rotl32(x1, ra[i]); x1 ^= x0; }
    x0 += ks0; x1 += ks1 + 3u;
#pragma unroll
    for (int i = 0; i < 4; i++) { x0 += x1; x1 = rotl32(x1, rb[i]); x1 ^= x0; }
    x0 += ks1; x1 += ks2 + 4u;
#pragma unroll
    for (int i = 0; i < 4; i++) { x0 += x1; x1 = rotl32(x1, ra[i]); x1 ^= x0; }
    x0 += ks2; x1 += ks0 + 5u;
    o0 = x0; o1 = x1;
}

// JAX threefry_partitionable random_bits (32-bit): counter = uint64 iota ->
// threefry2x32(key, 0, i), bits = o0 ^ o1. uniform = bitcast((bits>>9)|1.0f)-1.
__device__ float jax_uniform_noise(unsigned gid) {
    unsigned o0, o1;
    threefry2x32(0u, 1u, 0u, gid, o0, o1);
    unsigned bits = o0 ^ o1;
    unsigned fb = (bits >> 9) | 0x3f800000u;
    return __uint_as_float(fb) - 1.0f;
}

// ---------------- glibc expf (bit-exact port of sysdeps/ieee754/flt-32/e_expf.c) ----
__device__ __constant__ unsigned long long c_exp_tab[32] = {
    0x3ff0000000000000ULL, 0x3fefd9b0d3158574ULL, 0x3fefb5586cf9890fULL, 0x3fef9301d0125b51ULL,
    0x3fef72b83c7d517bULL, 0x3fef54873168b9aaULL, 0x3fef387a6e756238ULL, 0x3fef1e9df51fdee1ULL,
    0x3fef06fe0a31b715ULL, 0x3feef1a7373aa9cbULL, 0x3feedea64c123422ULL, 0x3feece086061892dULL,
    0x3feebfdad5362a27ULL, 0x3feeb42b569d4f82ULL, 0x3feeab07dd485429ULL, 0x3feea47eb03a5585ULL,
    0x3feea09e667f3bcdULL, 0x3fee9f75e8ec5f74ULL, 0x3feea11473eb0187ULL, 0x3feea589994cce13ULL,
    0x3feeace5422aa0dbULL, 0x3feeb737b0cdc5e5ULL, 0x3feec49182a3f090ULL, 0x3feed503b23e255dULL,
    0x3feee89f995ad3adULL, 0x3feeff76f2fb5e47ULL, 0x3fef199bdd85529cULL, 0x3fef3720dcef9069ULL,
    0x3fef5818dcfba487ULL, 0x3fef7c97337b9b5fULL, 0x3fefa4afa2a490daULL, 0x3fefd0765b6e4540ULL
};

__device__ float glibc_expf(float x) {
    const double InvLn2N = 0x1.71547652b82fep+5;          // N/ln2, N=32
    const double C0 = 0x1.c6af84b912394p-5 / (32.0 * 32.0 * 32.0);
    const double C1 = 0x1.ebfce50fac4f3p-3 / (32.0 * 32.0);
    const double C2 = 0x1.62e42ff0c52d6p-1 / 32.0;
    double xd = (double)x;
    double z  = InvLn2N * xd;
    double kd = rint(z);
    long long kis = __double2ll_rn(z);
    unsigned long long ki = (unsigned long long)kis;
    double r = z - kd;
    unsigned long long t = c_exp_tab[ki & 31] + (ki << 47);
    double s = __longlong_as_double((long long)t);
    double zz = fma(C0, r, C1);
    double r2 = r * r;
    double y  = fma(C2, r, 1.0);
    y = fma(zz, r2, y);
    return (float)(y * s);
}

// ---------------- f32x2 packed helpers ----------------
__device__ __forceinline__ unsigned long long pack_dup_f32(float a) {
    unsigned long long r;
    unsigned ai = __float_as_uint(a);
    asm("mov.b64 %0, {%1, %1};" : "=l"(r) : "r"(ai));
    return r;
}
__device__ __forceinline__ void fma2(unsigned long long& acc, unsigned long long a,
                                     unsigned long long b) {
    asm("fma.rn.f32x2 %0, %1, %2, %0;" : "+l"(acc) : "l"(a), "l"(b));
}
__device__ __forceinline__ void unpack2(unsigned long long v, float& lo, float& hi) {
    unsigned l, h;
    asm("mov.b64 {%0, %1}, %2;" : "=r"(l), "=r"(h) : "l"(v));
    lo = __uint_as_float(l); hi = __uint_as_float(h);
}

// ---------------- kernels ----------------

// no-op: shifts the ncu capture ordinal so knn_density_kernel gets profiled
__global__ void nop_kernel() {}

// x2 = sum(x*x, -1): 4 lane accumulators over k mod 4, unfused mul+add,
// horizontal combine (a0+a2)+(a1+a3). Also resets g_maxbits.
__global__ void x2_kernel(const float* __restrict__ x) {
    int row = blockIdx.x * blockDim.x + threadIdx.x;
    if (blockIdx.x == 0 && threadIdx.x < BB) g_maxbits[threadIdx.x] = 0u;
    if (row >= BB * NN) return;
    const float4* xp = (const float4*)(x + (size_t)row * CC);
    float a0 = 0.f, a1 = 0.f, a2 = 0.f, a3 = 0.f;
#pragma unroll 8
    for (int kb = 0; kb < CC / 4; kb++) {
        float4 v = xp[kb];
        a0 = __fadd_rn(a0, __fmul_rn(v.x, v.x));
        a1 = __fadd_rn(a1, __fmul_rn(v.y, v.y));
        a2 = __fadd_rn(a2, __fmul_rn(v.z, v.z));
        a3 = __fadd_rn(a3, __fmul_rn(v.w, v.w));
    }
    g_x2[row] = __fadd_rn(__fadd_rn(a0, a2), __fadd_rn(a1, a3));
}

// Triangular distance GEMM, 128x128 block tile, thread tile 8x8, packed
// fma.rn.f32x2, double-buffered smem, XOR-swizzled transpose stores,
// 1 barrier per K-chunk, 2 CTAs/SM. Bit-exact ascending-k chains.
#define NTILE 32            // NN/128
#define NPAIRS 528          // NTILE*(NTILE+1)/2
#define KCH 16
#define NCHUNK (CC / KCH)   // 16
__device__ __forceinline__ int tri_base(int i) { return i * (2 * NTILE + 1 - i) / 2; }

__global__ __launch_bounds__(256, 2) void dist_kernel(const float* __restrict__ x) {
    const int TS = 128;
    int b = blockIdx.z;
    int l = blockIdx.x;
    int ti = (int)((2 * NTILE + 1 - sqrtf((float)((2 * NTILE + 1) * (2 * NTILE + 1) - 8 * l))) * 0.5f);
    if (ti > 0 && tri_base(ti) > l) ti--;
    while (tri_base(ti + 1) <= l) ti++;
    int tj = ti + (l - tri_base(ti));
    int it = ti * TS;
    int jt = tj * TS;
    const float* xb = x + (size_t)b * NN * CC;

    __shared__ __align__(16) float As[2][KCH][TS];   // 16 KB
    __shared__ __align__(16) float Bs[2][KCH][TS];   // 16 KB

    int tid = threadIdx.x;          // 256 threads
    int tx = tid & 15, ty = tid >> 4;

    int rowb  = tid >> 2;           // 0..63
    int kk0   = (tid & 3) * 4;
    int swsto = (tid & 3) << 3;     // store-side swizzle = ((k>>2)&3)<<3
    const float* aptr = &xb[(size_t)(it + rowb) * CC + kk0];
    const float* bptr = &xb[(size_t)(jt + rowb) * CC + kk0];

    unsigned long long acc2[8][4];  // [u][vpair]
#pragma unroll
    for (int u = 0; u < 8; u++)
#pragma unroll
        for (int vp = 0; vp < 4; vp++) acc2[u][vp] = 0ULL;

    float4 pa0, pa1, pb0, pb1;
#define LOAD_CHUNK(k0n)                                 \
    do {                                                \
        pa0 = *(const float4*)(aptr + (k0n));           \
        pa1 = *(const float4*)(aptr + 64 * CC + (k0n)); \
        pb0 = *(const float4*)(bptr + (k0n));           \
        pb1 = *(const float4*)(bptr + 64 * CC + (k0n)); \
    } while (0)

#define STORE_CHUNK(buf)                                          \
    do {                                                          \
        int rc0 = rowb ^ swsto;                                   \
        int rc1 = (rowb + 64) ^ swsto;                            \
        As[buf][kk0 + 0][rc0] = pa0.x; As[buf][kk0 + 1][rc0] = pa0.y; \
        As[buf][kk0 + 2][rc0] = pa0.z; As[buf][kk0 + 3][rc0] = pa0.w; \
        As[buf][kk0 + 0][rc1] = pa1.x; As[buf][kk0 + 1][rc1] = pa1.y; \
        As[buf][kk0 + 2][rc1] = pa1.z; As[buf][kk0 + 3][rc1] = pa1.w; \
        Bs[buf][kk0 + 0][rc0] = pb0.x; Bs[buf][kk0 + 1][rc0] = pb0.y; \
        Bs[buf][kk0 + 2][rc0] = pb0.z; Bs[buf][kk0 + 3][rc0] = pb0.w; \
        Bs[buf][kk0 + 0][rc1] = pb1.x; Bs[buf][kk0 + 1][rc1] = pb1.y; \
        Bs[buf][kk0 + 2][rc1] = pb1.z; Bs[buf][kk0 + 3][rc1] = pb1.w; \
    } while (0)

    LOAD_CHUNK(0);
    STORE_CHUNK(0);
    __syncthreads();

    for (int chunk = 0; chunk < NCHUNK; chunk++) {
        int cur = chunk & 1;
        if (chunk + 1 < NCHUNK) LOAD_CHUNK((chunk + 1) * KCH);
#pragma unroll
        for (int kc = 0; kc < KCH; kc++) {
            const int swz = ((kc >> 2) & 3) << 3;
            float4 a0 = *(const float4*)(&As[cur][kc][(ty * 8) ^ swz]);
            float4 a1 = *(const float4*)(&As[cur][kc][(ty * 8 + 4) ^ swz]);
            double2 bd0 = *(const double2*)(&Bs[cur][kc][(tx * 8) ^ swz]);
            double2 bd1 = *(const double2*)(&Bs[cur][kc][(tx * 8 + 4) ^ swz]);
            unsigned long long b2[4];
            b2[0] = __double_as_longlong(bd0.x);
            b2[1] = __double_as_longlong(bd0.y);
            b2[2] = __double_as_longlong(bd1.x);
            b2[3] = __double_as_longlong(bd1.y);
            float a[8] = {a0.x, a0.y, a0.z, a0.w, a1.x, a1.y, a1.z, a1.w};
#pragma unroll
            for (int u = 0; u < 8; u++) {
                unsigned long long a2 = pack_dup_f32(a[u]);
#pragma unroll
                for (int vp = 0; vp < 4; vp++)
                    fma2(acc2[u][vp], a2, b2[vp]);
            }
        }
        if (chunk + 1 < NCHUNK) {
            STORE_CHUNK(cur ^ 1);
            __syncthreads();
        }
    }

    float acc[8][8];
#pragma unroll
    for (int u = 0; u < 8; u++)
#pragma unroll
        for (int vp = 0; vp < 4; vp++)
            unpack2(acc2[u][vp], acc[u][2 * vp], acc[u][2 * vp + 1]);

    float x2i[8], x2j[8];
#pragma unroll
    for (int u = 0; u < 8; u++) x2i[u] = g_x2[b * NN + it + ty * 8 + u];
#pragma unroll
    for (int v = 0; v < 8; v++) x2j[v] = g_x2[b * NN + jt + tx * 8 + v];
    unsigned mbits = 0u;
#pragma unroll
    for (int u = 0; u < 8; u++) {
#pragma unroll
        for (int v = 0; v < 8; v++) {
            float s  = __fadd_rn(x2i[u], x2j[v]);
            float d2 = __fadd_rn(s, -__fmul_rn(2.0f, acc[u][v]));
            d2 = fmaxf(d2, 0.0f);
            float d = __fmul_rn(__fsqrt_rn(d2), 0.0625f);
            acc[u][v] = d;
            mbits = max(mbits, __float_as_uint(d));
        }
    }
    mbits = __reduce_max_sync(0xffffffffu, mbits);
    if ((tid & 31) == 0) atomicMax(&g_maxbits[b], mbits);

#pragma unroll
    for (int u = 0; u < 8; u++) {
        float* drow = g_dist + ((size_t)b * NN + it + ty * 8 + u) * NN + jt + tx * 8;
        *(float4*)(drow)     = make_float4(acc[u][0], acc[u][1], acc[u][2], acc[u][3]);
        *(float4*)(drow + 4) = make_float4(acc[u][4], acc[u][5], acc[u][6], acc[u][7]);
    }
    if (it != jt) {
#pragma unroll
        for (int v = 0; v < 8; v++) {
            float* drow = g_dist + ((size_t)b * NN + jt + tx * 8 + v) * NN + it + ty * 8;
            *(float4*)(drow)     = make_float4(acc[0][v], acc[1][v], acc[2][v], acc[3][v]);
            *(float4*)(drow + 4) = make_float4(acc[4][v], acc[5][v], acc[6][v], acc[7][v]);
        }
    }
}

// per-row 32 smallest via sorted streams:
// 1) each thread bitonic-sorts its 16 values in registers (indices compile-time)
// 2) sorted values -> smem [r*256 + tid] (conflict-free)
// 3) per-warp head-pointer tournament extracts warp top-32 ascending (sync-free)
// 4) warp 0 merges the 8 sorted streams; lane 0 accumulates density sum in
//    reference order (ascending, mod-4 lanes, unfused mul+add).
__global__ void knn_density_kernel() {
    int row = blockIdx.x;                 // b*NN + i
    const float4* dr4 = (const float4*)(g_dist + (size_t)row * NN);
    int tid  = threadIdx.x;               // 256
    int lane = tid & 31, wid = tid >> 5;
    const unsigned REMOVED = 0xFFFFFFFFu;

    __shared__ unsigned svals[16 * 256];        // 16 KB: [r*256 + tid]
    __shared__ unsigned warpsel[8][KNNK];       // 1 KB

    unsigned v[16];
#pragma unroll
    for (int i = 0; i < 4; i++) {
        float4 f = dr4[tid + 256 * i];
        v[i * 4 + 0] = __float_as_uint(f.x);
        v[i * 4 + 1] = __float_as_uint(f.y);
        v[i * 4 + 2] = __float_as_uint(f.z);
        v[i * 4 + 3] = __float_as_uint(f.w);
    }

    // bitonic sort 16 ascending; all indices & directions compile-time constants
#pragma unroll
    for (int k = 2; k <= 16; k <<= 1) {
#pragma unroll
        for (int j = k >> 1; j > 0; j >>= 1) {
#pragma unroll
            for (int i = 0; i < 16; i++) {
                int l2 = i ^ j;
                if (l2 > i) {
                    unsigned lo = min(v[i], v[l2]);
                    unsigned hi = max(v[i], v[l2]);
                    if ((i & k) == 0) { v[i] = lo; v[l2] = hi; }
                    else              { v[i] = hi; v[l2] = lo; }
                }
            }
        }
    }

#pragma unroll
    for (int r = 0; r < 16; r++) svals[r * 256 + tid] = v[r];
    // warp-local streams: no block sync needed before phase 1 (each warp reads
    // only its own lanes' columns, written by the same warp)
    __syncwarp();

    // phase 1: per-warp top-32 ascending (head-pointer tournament, sync-free)
    unsigned hv = v[0];
    int h = 1;
    for (int it = 0; it < KNNK; it++) {
        unsigned m = __reduce_min_sync(0xffffffffu, hv);
        unsigned ball = __ballot_sync(0xffffffffu, hv == m);
        int owner = __ffs(ball) - 1;
        if (lane == owner) {
            hv = (h < 16) ? svals[h * 256 + tid] : REMOVED;
            h++;
        }
        if (lane == 0) warpsel[wid][it] = m;
    }
    __syncthreads();

    // phase 2: warp 0 merges 8 sorted streams of 32
    if (wid == 0) {
        unsigned hv2 = (lane < 8) ? warpsel[lane][0] : REMOVED;
        int h2 = 1;
        float a0 = 0.f, a1 = 0.f, a2 = 0.f, a3 = 0.f;
        for (int it = 0; it < KNNK; it++) {
            unsigned m = __reduce_min_sync(0xffffffffu, hv2);
            unsigned ball = __ballot_sync(0xffffffffu, hv2 == m);
            int owner = __ffs(ball) - 1;
            if (lane == owner) {
                hv2 = (h2 < KNNK) ? warpsel[lane][h2] : REMOVED;
                h2++;
            }
            if (lane == 0) {
                float d = __uint_as_float(m);
                float sq = __fmul_rn(d, d);
                if ((it & 3) == 0) a0 = __fadd_rn(a0, sq);
                else if ((it & 3) == 1) a1 = __fadd_rn(a1, sq);
                else if ((it & 3) == 2) a2 = __fadd_rn(a2, sq);
                else a3 = __fadd_rn(a3, sq);
            }
        }
        if (lane == 0) {
            float sum  = __fadd_rn(__fadd_rn(a0, a2), __fadd_rn(a1, a3));
            float mean = __fmul_rn(sum, 0.03125f);
            float dens = glibc_expf(-mean);
            float noise = jax_uniform_noise((unsigned)row);
            g_density[row] = __fadd_rn(dens, __fmul_rn(noise, 1e-6f));
        }
    }
}

// dist-to-nearest-higher-density (vectorized, order-free min), score = dist*density
__global__ void distmin_kernel() {
    int row = blockIdx.x;
    int b = row >> 12;
    const float4* dr4   = (const float4*)(g_dist + (size_t)row * NN);
    const float4* dens4 = (const float4*)(g_density + b * NN);
    float di   = g_density[row];
    float mv = __uint_as_float(g_maxbits[b]);
    int tid = threadIdx.x;
#pragma unroll
    for (int i = 0; i < 4; i++) {
        float4 d = dr4[tid + 256 * i];
        float4 e = dens4[tid + 256 * i];
        if (e.x > di) mv = fminf(mv, d.x);
        if (e.y > di) mv = fminf(mv, d.y);
        if (e.z > di) mv = fminf(mv, d.z);
        if (e.w > di) mv = fminf(mv, d.w);
    }
    unsigned mb = __reduce_min_sync(0xffffffffu, __float_as_uint(mv));
    __shared__ unsigned sm[8];
    if ((tid & 31) == 0) sm[tid >> 5] = mb;
    __syncthreads();
    if (tid == 0) {
        unsigned mm = sm[0];
#pragma unroll
        for (int w = 1; w < 8; w++) mm = min(mm, sm[w]);
        g_score[row] = __fmul_rn(__uint_as_float(mm), di);
    }
}

// bitonic sort, key = (~score_bits << 32) | idx  -> top-K with lax.top_k ties
__global__ void topk_kernel(float* __restrict__ out_indexdown) {
    __shared__ unsigned long long keys[NN];   // 32 KB
    int b = blockIdx.x;
    int tid = threadIdx.x;                    // 512 threads
    for (int j = tid; j < NN; j += 512) {
        unsigned sb = __float_as_uint(g_score[b * NN + j]);
        keys[j] = ((unsigned long long)(~sb) << 32) | (unsigned)j;
    }
    __syncthreads();
    for (unsigned k = 2; k <= NN; k <<= 1) {
        for (unsigned st = k >> 1; st > 0; st >>= 1) {
            for (unsigned i = tid; i < NN; i += 512) {
                unsigned ixj = i ^ st;
                if (ixj > i) {
                    unsigned long long a = keys[i], c = keys[ixj];
                    bool up = ((i & k) == 0);
                    bool swap = up ? (a > c) : (a < c);
                    if (swap) { keys[i] = c; keys[ixj] = a; }
                }
            }
            __syncthreads();
        }
    }
    int idx = (int)(keys[tid] & 0xFFFFFFFFull);
    g_index_down[b * KK + tid] = idx;
    out_indexdown[b * KK + tid] = (float)idx;
}

// idx_cluster[b,j] = argmin_kk dist[b, center_kk, j]  (first-min, strict <)
__global__ void assign_kernel(float* __restrict__ out_idxcluster) {
    int b = blockIdx.y;
    int j = blockIdx.x * 256 + threadIdx.x;
    __shared__ int cen[KK];
    for (int t = threadIdx.x; t < KK; t += 256) cen[t] = g_index_down[b * KK + t];
    __syncthreads();
    const float* db = g_dist + (size_t)b * NN * NN;
    float best = 3.4e38f; int bi = 0;
    for (int kk = 0; kk < KK; kk++) {
        float v = db[(size_t)cen[kk] * NN + j];
        if (v < best) { best = v; bi = kk; }
    }
    out_idxcluster[b * NN + j] = (float)bi;
}

__global__ void scatter_kernel(float* __restrict__ out_idxcluster) {
    int t = blockIdx.x * 256 + threadIdx.x;
    if (t >= BB * KK) return;
    int b = t >> 9, kk = t & (KK - 1);
    out_idxcluster[b * NN + g_index_down[t]] = (float)kk;
}

__global__ void xdown_kernel(const float* __restrict__ x, float* __restrict__ out_xdown) {
    int t = blockIdx.x * 256 + threadIdx.x;
    if (t >= BB * KK * CC) return;
    int c = t & (CC - 1);
    int rest = t >> 8;
    int kk = rest & (KK - 1);
    int b = rest >> 9;
    out_xdown[t] = x[((size_t)b * NN + g_index_down[b * KK + kk]) * CC + c];
}

// ---------------- launch ----------------
extern "C" void kernel_launch(void* const* d_in, const int* in_sizes, int n_in,
                              void* d_out, int out_size) {
    const float* x = (const float*)d_in[0];
    float* out = (float*)d_out;
    float* out_indexdown  = out;                       // B*K
    float* out_idxcluster = out + BB * KK;             // B*N
    float* out_xdown      = out + BB * KK + BB * NN;   // B*K*C

    x2_kernel<<<(BB * NN + 255) / 256, 256>>>(x);

    dim3 gg(NPAIRS, 1, BB);
    dist_kernel<<<gg, 256>>>(x);

    // keep ncu's fixed 4th-launch capture on knn_density_kernel
    nop_kernel<<<1, 32>>>();

    knn_density_kernel<<<BB * NN, 256>>>();

    distmin_kernel<<<BB * NN, 256>>>();

    topk_kernel<<<BB, 512>>>(out_indexdown);

    assign_kernel<<<dim3(NN / 256, BB), 256>>>(out_idxcluster);
    scatter_kernel<<<(BB * KK + 255) / 256, 256>>>(out_idxcluster);
    xdown_kernel<<<(BB * KK * CC + 255) / 256, 256>>>(x, out_xdown);
}